// round 2
// baseline (speedup 1.0000x reference)
#include <cuda_runtime.h>
#include <cuda_bf16.h>

#define BB 8
#define CC 2048
#define FIN 128
#define FF 64
#define NROWS (BB*CC)

// Scratch (allocation-free rule: __device__ globals)
__device__ float g_Wh[(size_t)NROWS * FF];
__device__ float g_s1[NROWS];
__device__ float g_s2[NROWS];
__device__ float g_m[NROWS];
__device__ float g_l[NROWS];

// ---------------------------------------------------------------------------
// Kernel 1: Wh = H @ W  (per-row), plus s1 = Wh·a1, s2 = Wh·a2
// One warp per row. W staged in shared memory per block (8 warps / block).
// ---------------------------------------------------------------------------
__global__ __launch_bounds__(256) void k_wh(const float* __restrict__ H,
                                            const float* __restrict__ W,
                                            const float* __restrict__ a)
{
    __shared__ float Ws[FIN * FF];
    int t = threadIdx.x;
    for (int i = t; i < FIN * FF; i += 256) Ws[i] = W[i];
    __syncthreads();

    int warp = t >> 5, lane = t & 31;
    int r = blockIdx.x * 8 + warp;        // row in [0, NROWS)
    const float* hrow = H + (size_t)r * FIN;
    float h0 = hrow[lane], h1 = hrow[lane + 32], h2 = hrow[lane + 64], h3 = hrow[lane + 96];

    float acc0 = 0.f, acc1 = 0.f;
#pragma unroll
    for (int k = 0; k < FIN; k++) {
        float src = (k < 32) ? h0 : (k < 64) ? h1 : (k < 96) ? h2 : h3;
        float hk = __shfl_sync(0xffffffffu, src, k & 31);
        acc0 = fmaf(hk, Ws[k * FF + lane], acc0);
        acc1 = fmaf(hk, Ws[k * FF + lane + 32], acc1);
    }

    // s1/s2 reductions
    float p1 = acc0 * a[lane] + acc1 * a[lane + 32];
    float p2 = acc0 * a[FF + lane] + acc1 * a[FF + lane + 32];
#pragma unroll
    for (int off = 16; off; off >>= 1) {
        p1 += __shfl_xor_sync(0xffffffffu, p1, off);
        p2 += __shfl_xor_sync(0xffffffffu, p2, off);
    }
    if (lane == 0) { g_s1[r] = p1; g_s2[r] = p2; }

    g_Wh[(size_t)r * FF + lane]      = acc0;
    g_Wh[(size_t)r * FF + 32 + lane] = acc1;
}

// ---------------------------------------------------------------------------
// Kernel 2: per-row softmax stats (max m, denom l) with online update.
// One warp per row; lanes stride over the 2048 neighbors (coalesced A reads).
// Masked entries contribute exp(-1e9) == 0, so they are simply skipped;
// the diagonal is always valid, guaranteeing l >= 1 per row.
// ---------------------------------------------------------------------------
__global__ __launch_bounds__(256) void k_stats(const int* __restrict__ A)
{
    int t = threadIdx.x;
    int warp = t >> 5, lane = t & 31;
    int r = blockIdx.x * 8 + warp;
    int b = r / CC, i = r % CC;

    const int* arow = A + (size_t)b * CC * CC + (size_t)i * CC;
    const float* s2b = g_s2 + b * CC;
    float s1i = g_s1[r];

    float m = -1e30f, l = 0.f;
    for (int j = lane; j < CC; j += 32) {
        int av = arow[j];
        bool valid = (av > 0) || (j == i);
        if (valid) {
            float x = s1i + s2b[j];
            x = (x > 0.f) ? x : 0.2f * x;
            if (x > m) { l = l * __expf(m - x) + 1.f; m = x; }
            else       { l += __expf(x - m); }
        }
    }
    // merge lane-local (m,l) states
#pragma unroll
    for (int off = 16; off; off >>= 1) {
        float mo = __shfl_xor_sync(0xffffffffu, m, off);
        float lo = __shfl_xor_sync(0xffffffffu, l, off);
        float mn = fmaxf(m, mo);
        l = l * __expf(m - mn) + lo * __expf(mo - mn);
        m = mn;
    }
    if (lane == 0) { g_m[r] = m; g_l[r] = l; }
}

// ---------------------------------------------------------------------------
// Kernel 3: out = relu( softmax(e) @ Wh ).
// Block tile: TM=64 rows x all 64 features, loop over j in TJ=64 tiles.
// p tile (exp weights) materialized in smem, then 4x4 register-blocked FMA.
// ---------------------------------------------------------------------------
#define TM 64
#define TJ 64

__global__ __launch_bounds__(256) void k_out(const int* __restrict__ A,
                                             float* __restrict__ out)
{
    __shared__ float whs[TJ][FF];
    __shared__ float ps[TM][TJ + 1];     // +1 pad: avoid 16-way bank conflicts
    __shared__ float s1s[TM], ms[TM], ls[TM], s2s[TJ];

    int t = threadIdx.x;
    int b  = blockIdx.x >> 5;            // 32 row-tiles per batch
    int i0 = (blockIdx.x & 31) << 6;
    int rbase = b * CC + i0;

    if (t < TM) { s1s[t] = g_s1[rbase + t]; ms[t] = g_m[rbase + t]; ls[t] = g_l[rbase + t]; }

    int tx = t & 15, ty = t >> 4;        // tx: 4-feature group, ty: row slice
    float acc[4][4] = {};

    const int* Ab = A + (size_t)b * CC * CC;

    for (int j0 = 0; j0 < CC; j0 += TJ) {
        __syncthreads();                 // protects smem reuse + initial loads
        if (t < TJ) s2s[t] = g_s2[b * CC + j0 + t];
        {
            const float4* src = (const float4*)(g_Wh + ((size_t)(b * CC + j0)) * FF);
            float4* dst = (float4*)&whs[0][0];
            for (int k = t; k < TJ * FF / 4; k += 256) dst[k] = src[k];
        }
        __syncthreads();

        // p tile: each thread covers fixed jl, 16 rows (coalesced A reads)
        int jl  = t & 63;
        int ilb = t >> 6;
        float s2v = s2s[jl];
#pragma unroll
        for (int rr = 0; rr < 16; rr++) {
            int il = ilb * 16 + rr;
            int av = Ab[(size_t)(i0 + il) * CC + j0 + jl];
            bool valid = (av > 0) || (i0 + il == j0 + jl);
            float x = s1s[il] + s2v;
            x = (x > 0.f) ? x : 0.2f * x;
            ps[il][jl] = valid ? __expf(x - ms[il]) : 0.f;
        }
        __syncthreads();

        // acc += p @ Wh_tile (4 rows x 4 features per thread)
#pragma unroll
        for (int jl2 = 0; jl2 < TJ; jl2++) {
            float4 w = *(const float4*)&whs[jl2][tx * 4];
#pragma unroll
            for (int rr = 0; rr < 4; rr++) {
                float p = ps[ty + rr * 16][jl2];
                acc[rr][0] = fmaf(p, w.x, acc[rr][0]);
                acc[rr][1] = fmaf(p, w.y, acc[rr][1]);
                acc[rr][2] = fmaf(p, w.z, acc[rr][2]);
                acc[rr][3] = fmaf(p, w.w, acc[rr][3]);
            }
        }
    }

    // epilogue: normalize by l, relu, store
#pragma unroll
    for (int rr = 0; rr < 4; rr++) {
        int il = ty + rr * 16;
        float inv = 1.f / ls[il];
        float4 v;
        v.x = fmaxf(acc[rr][0] * inv, 0.f);
        v.y = fmaxf(acc[rr][1] * inv, 0.f);
        v.z = fmaxf(acc[rr][2] * inv, 0.f);
        v.w = fmaxf(acc[rr][3] * inv, 0.f);
        *(float4*)(out + ((size_t)(b * CC + i0 + il)) * FF + tx * 4) = v;
    }
}

// ---------------------------------------------------------------------------
extern "C" void kernel_launch(void* const* d_in, const int* in_sizes, int n_in,
                              void* d_out, int out_size)
{
    const float* H = (const float*)d_in[0];   // (8, 2048, 128) f32
    const int*   A = (const int*)d_in[1];     // (8, 2048, 2048) i32
    const float* W = (const float*)d_in[2];   // (128, 64) f32
    const float* a = (const float*)d_in[3];   // (128,) f32
    float* out = (float*)d_out;               // (8, 2048, 64) f32

    k_wh<<<NROWS / 8, 256>>>(H, W, a);
    k_stats<<<NROWS / 8, 256>>>(A);
    k_out<<<(BB * CC) / TM, 256>>>(A, out);
}

// round 4
// speedup vs baseline: 1.3173x; 1.3173x over previous
#include <cuda_runtime.h>
#include <cuda_bf16.h>
#include <cstdint>

#define BB 8
#define CC 2048
#define FIN 128
#define FF 64
#define NROWS (BB*CC)

// Scratch (__device__ globals: allocation-free rule)
__device__ float g_Wh[(size_t)NROWS * FF];   // fp32 Wh
__device__ float g_s1[NROWS];
__device__ float g_s2[NROWS];

__device__ __forceinline__ float f2tf32f(float x) {
    uint32_t r;
    asm("cvt.rna.tf32.f32 %0, %1;" : "=r"(r) : "f"(x));
    return __uint_as_float(r);
}

__device__ __forceinline__ void mma_tf32(float c[4],
                                         uint32_t a0, uint32_t a1, uint32_t a2, uint32_t a3,
                                         uint32_t b0, uint32_t b1) {
    asm volatile(
        "mma.sync.aligned.m16n8k8.row.col.f32.tf32.tf32.f32 "
        "{%0,%1,%2,%3}, {%4,%5,%6,%7}, {%8,%9}, {%0,%1,%2,%3};"
        : "+f"(c[0]), "+f"(c[1]), "+f"(c[2]), "+f"(c[3])
        : "r"(a0), "r"(a1), "r"(a2), "r"(a3), "r"(b0), "r"(b1));
}

// ---------------------------------------------------------------------------
// Kernel 1: Wh = H @ W (tiled GEMM, 128 rows/block), + s1 = Wh·a1, s2 = Wh·a2.
// Full fp32 throughout; tf32 rounding happens at use site in k_out.
// ---------------------------------------------------------------------------
__global__ __launch_bounds__(256) void k_wh(const float* __restrict__ H,
                                            const float* __restrict__ W,
                                            const float* __restrict__ a)
{
    __shared__ float Hs[128][36];     // 128 rows x 32 k (padded)
    __shared__ float Ws[32][68];      // 32 k x 64 cols (padded)

    int t  = threadIdx.x;
    int tx = t & 15, ty = t >> 4;     // tx: col group (4 cols), ty: 8-row group
    int r0 = blockIdx.x * 128;

    float acc[8][4] = {};

    for (int kc = 0; kc < 4; kc++) {
        __syncthreads();
        {   // H tile: 128 rows x 32 k
            int row = t >> 3, q = t & 7;
            const float* src = H + (size_t)r0 * FIN + kc * 32;
#pragma unroll
            for (int p = 0; p < 4; p++) {
                int rr = p * 32 + row;
                *(float4*)&Hs[rr][q * 4] = *(const float4*)(src + (size_t)rr * FIN + q * 4);
            }
        }
        {   // W chunk: 32 k x 64 cols
#pragma unroll
            for (int p = 0; p < 2; p++) {
                int idx = t + p * 256;
                int row = idx >> 4, c4 = idx & 15;
                *(float4*)&Ws[row][c4 * 4] = *(const float4*)(W + (size_t)(kc * 32 + row) * FF + c4 * 4);
            }
        }
        __syncthreads();

#pragma unroll
        for (int k = 0; k < 32; k++) {
            float4 w = *(const float4*)&Ws[k][tx * 4];
#pragma unroll
            for (int rr = 0; rr < 8; rr++) {
                float h = Hs[ty * 8 + rr][k];
                acc[rr][0] = fmaf(h, w.x, acc[rr][0]);
                acc[rr][1] = fmaf(h, w.y, acc[rr][1]);
                acc[rr][2] = fmaf(h, w.z, acc[rr][2]);
                acc[rr][3] = fmaf(h, w.w, acc[rr][3]);
            }
        }
    }

    float a1v[4], a2v[4];
#pragma unroll
    for (int c = 0; c < 4; c++) { a1v[c] = a[tx * 4 + c]; a2v[c] = a[FF + tx * 4 + c]; }

#pragma unroll
    for (int rr = 0; rr < 8; rr++) {
        int r = r0 + ty * 8 + rr;
        float p1 = 0.f, p2 = 0.f;
#pragma unroll
        for (int c = 0; c < 4; c++) {
            p1 = fmaf(acc[rr][c], a1v[c], p1);
            p2 = fmaf(acc[rr][c], a2v[c], p2);
        }
#pragma unroll
        for (int off = 8; off; off >>= 1) {
            p1 += __shfl_xor_sync(0xffffffffu, p1, off);
            p2 += __shfl_xor_sync(0xffffffffu, p2, off);
        }
        if (tx == 0) { g_s1[r] = p1; g_s2[r] = p2; }

        *(float4*)(g_Wh + (size_t)r * FF + tx * 4) = *(float4*)acc[rr];
    }
}

// ---------------------------------------------------------------------------
// Kernel 2: fused masked-softmax @ Wh.  64 rows/block, 128 threads (4 warps).
// Pass 1: one streamed read of the 64x2048 A strip -> smem bitmask + exact
//         per-row max (via max of valid s2; lrelu monotone => exact row max,
//         so p_max = 1 and l >= 1: no underflow possible).
// Pass 2: p computed straight into MMA A-fragments (each exp once), Wh tiles
//         tf32-rounded in smem; ones-column gives l as MMA output col 64.
// ---------------------------------------------------------------------------
__global__ __launch_bounds__(128) void k_out(const int* __restrict__ A,
                                             float* __restrict__ out)
{
    __shared__ uint32_t maskS[64][65];   // validity bitmask (65: kill bank conflicts)
    __shared__ float s2S[CC];            // all s2 of this batch
    __shared__ float whs[64][72];        // Wh tile (tf32) + ones col + pad
    __shared__ float s1s[64], ms[64];

    int t = threadIdx.x;
    int lane = t & 31, warp = t >> 5;
    int g = lane >> 2, tg = lane & 3;
    int m0 = warp * 16;

    int b  = blockIdx.x >> 5;
    int i0 = (blockIdx.x & 31) << 6;
    const int* Ab = A + (size_t)b * CC * CC;

    if (t < 64) {
        s1s[t] = g_s1[b * CC + i0 + t];
        whs[t][64] = 1.f; whs[t][65] = 0.f; whs[t][66] = 0.f; whs[t][67] = 0.f;
        whs[t][68] = 0.f; whs[t][69] = 0.f; whs[t][70] = 0.f; whs[t][71] = 0.f;
    }
    for (int q = t; q < CC; q += 128) s2S[q] = g_s2[b * CC + q];
    __syncthreads();

    // ---- Pass 1: bitmask + exact row max (single A read) ----
    for (int rr = 0; rr < 16; rr++) {
        int il = warp * 16 + rr;
        const int* base = Ab + (size_t)(i0 + il) * CC;
        int diagj = i0 + il;
        float m2 = -3.0e38f;
#pragma unroll 4
        for (int wd = 0; wd < 64; wd++) {
            int j = wd * 32 + lane;
            int av = __ldcs(base + j);
            bool valid = (av > 0) || (j == diagj);
            unsigned bal = __ballot_sync(0xffffffffu, valid);
            if (lane == 0) maskS[il][wd] = bal;
            if (valid) m2 = fmaxf(m2, s2S[j]);
        }
#pragma unroll
        for (int off = 16; off; off >>= 1)
            m2 = fmaxf(m2, __shfl_xor_sync(0xffffffffu, m2, off));
        if (lane == 0) {
            float x = s1s[il] + m2;
            ms[il] = (x > 0.f) ? x : 0.2f * x;   // exact row max of lrelu logits
        }
    }
    __syncthreads();

    // hoist this thread's two row constants
    float s1a = s1s[m0 + g],     ma = ms[m0 + g];
    float s1b = s1s[m0 + g + 8], mb = ms[m0 + g + 8];
    const uint32_t* mwA = maskS[m0 + g];
    const uint32_t* mwB = maskS[m0 + g + 8];
    int diagA = i0 + m0 + g, diagB = i0 + m0 + g + 8;  // diag already in bitmask
    (void)diagA; (void)diagB;

    float acc[9][4] = {};

    for (int j0 = 0; j0 < CC; j0 += 64) {
        __syncthreads();                       // protect whs reuse
        {   // stage Wh tile, tf32-rounded
            const float4* src = (const float4*)(g_Wh + (size_t)(b * CC + j0) * FF);
#pragma unroll
            for (int p = 0; p < 8; p++) {
                int idx = t + p * 128;
                int row = idx >> 4, c4 = idx & 15;
                float4 v = src[idx];
                v.x = f2tf32f(v.x); v.y = f2tf32f(v.y);
                v.z = f2tf32f(v.z); v.w = f2tf32f(v.w);
                *(float4*)&whs[row][c4 * 4] = v;
            }
        }
        __syncthreads();

#pragma unroll
        for (int kk = 0; kk < 8; kk++) {
            int k0 = kk * 8;
            int jl0 = k0 + tg, jl1 = jl0 + 4;          // both in same 32-bit word
            int wrd = (j0 + k0) >> 5;
            int bit0 = ((j0 + k0) & 31) + tg, bit1 = bit0 + 4;
            uint32_t mA = mwA[wrd], mB = mwB[wrd];
            float s2v0 = s2S[j0 + jl0], s2v1 = s2S[j0 + jl1];

            float xa0 = s1a + s2v0; xa0 = (xa0 > 0.f) ? xa0 : 0.2f * xa0;
            float xa1 = s1a + s2v1; xa1 = (xa1 > 0.f) ? xa1 : 0.2f * xa1;
            float xb0 = s1b + s2v0; xb0 = (xb0 > 0.f) ? xb0 : 0.2f * xb0;
            float xb1 = s1b + s2v1; xb1 = (xb1 > 0.f) ? xb1 : 0.2f * xb1;

            float pa0 = ((mA >> bit0) & 1u) ? __expf(xa0 - ma) : 0.f;
            float pa1 = ((mA >> bit1) & 1u) ? __expf(xa1 - ma) : 0.f;
            float pb0 = ((mB >> bit0) & 1u) ? __expf(xb0 - mb) : 0.f;
            float pb1 = ((mB >> bit1) & 1u) ? __expf(xb1 - mb) : 0.f;

            // A-frag: a0=(row g, k tg) a1=(row g+8, k tg) a2=(row g, k tg+4) a3=(row g+8, k tg+4)
            uint32_t a0 = __float_as_uint(f2tf32f(pa0));
            uint32_t a1 = __float_as_uint(f2tf32f(pb0));
            uint32_t a2 = __float_as_uint(f2tf32f(pa1));
            uint32_t a3 = __float_as_uint(f2tf32f(pb1));

#pragma unroll
            for (int nf = 0; nf < 9; nf++) {
                uint32_t b0 = __float_as_uint(whs[jl0][nf * 8 + g]);
                uint32_t b1 = __float_as_uint(whs[jl1][nf * 8 + g]);
                mma_tf32(acc[nf], a0, a1, a2, a3, b0, b1);
            }
        }
    }

    // epilogue: l = col 64 (nf=8, tg=0 lanes) -> broadcast within quad
    float l_lo = __shfl_sync(0xffffffffu, acc[8][0], lane & ~3);
    float l_hi = __shfl_sync(0xffffffffu, acc[8][2], lane & ~3);
    float inv_lo = 1.f / l_lo;       // l >= 1 guaranteed (exact max in shift)
    float inv_hi = 1.f / l_hi;

    int row_lo = b * CC + i0 + m0 + g;
    int row_hi = row_lo + 8;
#pragma unroll
    for (int nf = 0; nf < 8; nf++) {
        int col = nf * 8 + 2 * tg;
        float2 vlo, vhi;
        vlo.x = fmaxf(acc[nf][0] * inv_lo, 0.f);
        vlo.y = fmaxf(acc[nf][1] * inv_lo, 0.f);
        vhi.x = fmaxf(acc[nf][2] * inv_hi, 0.f);
        vhi.y = fmaxf(acc[nf][3] * inv_hi, 0.f);
        *(float2*)(out + (size_t)row_lo * FF + col) = vlo;
        *(float2*)(out + (size_t)row_hi * FF + col) = vhi;
    }
}

// ---------------------------------------------------------------------------
extern "C" void kernel_launch(void* const* d_in, const int* in_sizes, int n_in,
                              void* d_out, int out_size)
{
    const float* H = (const float*)d_in[0];   // (8, 2048, 128) f32
    const int*   A = (const int*)d_in[1];     // (8, 2048, 2048) i32
    const float* W = (const float*)d_in[2];   // (128, 64) f32
    const float* a = (const float*)d_in[3];   // (128,) f32
    float* out = (float*)d_out;               // (8, 2048, 64) f32

    k_wh<<<NROWS / 128, 256>>>(H, W, a);
    k_out<<<BB * (CC / 64), 128>>>(A, out);
}

// round 5
// speedup vs baseline: 1.3306x; 1.0101x over previous
#include <cuda_runtime.h>
#include <cuda_bf16.h>
#include <cstdint>

#define BB 8
#define CC 2048
#define FIN 128
#define FF 64
#define NROWS (BB*CC)

// Scratch (__device__ globals: allocation-free rule)
__device__ float g_Wh[(size_t)NROWS * FF];   // fp32 Wh
__device__ float g_s1[NROWS];
__device__ float g_s2[NROWS];

__device__ __forceinline__ float f2tf32f(float x) {
    uint32_t r;
    asm("cvt.rna.tf32.f32 %0, %1;" : "=r"(r) : "f"(x));
    return __uint_as_float(r);
}

__device__ __forceinline__ void mma_tf32(float c[4],
                                         uint32_t a0, uint32_t a1, uint32_t a2, uint32_t a3,
                                         uint32_t b0, uint32_t b1) {
    asm volatile(
        "mma.sync.aligned.m16n8k8.row.col.f32.tf32.tf32.f32 "
        "{%0,%1,%2,%3}, {%4,%5,%6,%7}, {%8,%9}, {%0,%1,%2,%3};"
        : "+f"(c[0]), "+f"(c[1]), "+f"(c[2]), "+f"(c[3])
        : "r"(a0), "r"(a1), "r"(a2), "r"(a3), "r"(b0), "r"(b1));
}

// ---------------------------------------------------------------------------
// Kernel 1: Wh = H @ W (tiled GEMM, 128 rows/block), + s1 = Wh·a1, s2 = Wh·a2.
// Full fp32 throughout; tf32 rounding happens at use site in k_out.
// ---------------------------------------------------------------------------
__global__ __launch_bounds__(256) void k_wh(const float* __restrict__ H,
                                            const float* __restrict__ W,
                                            const float* __restrict__ a)
{
    __shared__ float Hs[128][36];     // 128 rows x 32 k (padded)
    __shared__ float Ws[32][68];      // 32 k x 64 cols (padded)

    int t  = threadIdx.x;
    int tx = t & 15, ty = t >> 4;     // tx: col group (4 cols), ty: 8-row group
    int r0 = blockIdx.x * 128;

    float acc[8][4] = {};

    for (int kc = 0; kc < 4; kc++) {
        __syncthreads();
        {   // H tile: 128 rows x 32 k
            int row = t >> 3, q = t & 7;
            const float* src = H + (size_t)r0 * FIN + kc * 32;
#pragma unroll
            for (int p = 0; p < 4; p++) {
                int rr = p * 32 + row;
                *(float4*)&Hs[rr][q * 4] = *(const float4*)(src + (size_t)rr * FIN + q * 4);
            }
        }
        {   // W chunk: 32 k x 64 cols
#pragma unroll
            for (int p = 0; p < 2; p++) {
                int idx = t + p * 256;
                int row = idx >> 4, c4 = idx & 15;
                *(float4*)&Ws[row][c4 * 4] = *(const float4*)(W + (size_t)(kc * 32 + row) * FF + c4 * 4);
            }
        }
        __syncthreads();

#pragma unroll
        for (int k = 0; k < 32; k++) {
            float4 w = *(const float4*)&Ws[k][tx * 4];
#pragma unroll
            for (int rr = 0; rr < 8; rr++) {
                float h = Hs[ty * 8 + rr][k];
                acc[rr][0] = fmaf(h, w.x, acc[rr][0]);
                acc[rr][1] = fmaf(h, w.y, acc[rr][1]);
                acc[rr][2] = fmaf(h, w.z, acc[rr][2]);
                acc[rr][3] = fmaf(h, w.w, acc[rr][3]);
            }
        }
    }

    float a1v[4], a2v[4];
#pragma unroll
    for (int c = 0; c < 4; c++) { a1v[c] = a[tx * 4 + c]; a2v[c] = a[FF + tx * 4 + c]; }

#pragma unroll
    for (int rr = 0; rr < 8; rr++) {
        int r = r0 + ty * 8 + rr;
        float p1 = 0.f, p2 = 0.f;
#pragma unroll
        for (int c = 0; c < 4; c++) {
            p1 = fmaf(acc[rr][c], a1v[c], p1);
            p2 = fmaf(acc[rr][c], a2v[c], p2);
        }
#pragma unroll
        for (int off = 8; off; off >>= 1) {
            p1 += __shfl_xor_sync(0xffffffffu, p1, off);
            p2 += __shfl_xor_sync(0xffffffffu, p2, off);
        }
        if (tx == 0) { g_s1[r] = p1; g_s2[r] = p2; }

        *(float4*)(g_Wh + (size_t)r * FF + tx * 4) = *(float4*)acc[rr];
    }
}

// ---------------------------------------------------------------------------
// Kernel 2: fused masked-softmax @ Wh.  64 rows/block, 128 threads (4 warps).
// Pass 1: one streamed read of the 64x2048 A strip -> smem bitmask + exact
//         per-row max (via max of valid s2; lrelu monotone => exact row max,
//         so p_max = 1 and l >= 1: no underflow possible).
// Pass 2: p computed straight into MMA A-fragments (each exp once), Wh tiles
//         tf32-rounded in smem; ones-column gives l as MMA output col 64.
// ---------------------------------------------------------------------------
__global__ __launch_bounds__(128) void k_out(const int* __restrict__ A,
                                             float* __restrict__ out)
{
    __shared__ uint32_t maskS[64][65];   // validity bitmask (65: kill bank conflicts)
    __shared__ float s2S[CC];            // all s2 of this batch
    __shared__ float whs[64][72];        // Wh tile (tf32) + ones col + pad
    __shared__ float s1s[64], ms[64];

    int t = threadIdx.x;
    int lane = t & 31, warp = t >> 5;
    int g = lane >> 2, tg = lane & 3;
    int m0 = warp * 16;

    int b  = blockIdx.x >> 5;
    int i0 = (blockIdx.x & 31) << 6;
    const int* Ab = A + (size_t)b * CC * CC;

    if (t < 64) {
        s1s[t] = g_s1[b * CC + i0 + t];
        whs[t][64] = 1.f; whs[t][65] = 0.f; whs[t][66] = 0.f; whs[t][67] = 0.f;
        whs[t][68] = 0.f; whs[t][69] = 0.f; whs[t][70] = 0.f; whs[t][71] = 0.f;
    }
    for (int q = t; q < CC; q += 128) s2S[q] = g_s2[b * CC + q];
    __syncthreads();

    // ---- Pass 1: bitmask + exact row max (single A read) ----
    for (int rr = 0; rr < 16; rr++) {
        int il = warp * 16 + rr;
        const int* base = Ab + (size_t)(i0 + il) * CC;
        int diagj = i0 + il;
        float m2 = -3.0e38f;
#pragma unroll 4
        for (int wd = 0; wd < 64; wd++) {
            int j = wd * 32 + lane;
            int av = __ldcs(base + j);
            bool valid = (av > 0) || (j == diagj);
            unsigned bal = __ballot_sync(0xffffffffu, valid);
            if (lane == 0) maskS[il][wd] = bal;
            if (valid) m2 = fmaxf(m2, s2S[j]);
        }
#pragma unroll
        for (int off = 16; off; off >>= 1)
            m2 = fmaxf(m2, __shfl_xor_sync(0xffffffffu, m2, off));
        if (lane == 0) {
            float x = s1s[il] + m2;
            ms[il] = (x > 0.f) ? x : 0.2f * x;   // exact row max of lrelu logits
        }
    }
    __syncthreads();

    // hoist this thread's two row constants
    float s1a = s1s[m0 + g],     ma = ms[m0 + g];
    float s1b = s1s[m0 + g + 8], mb = ms[m0 + g + 8];
    const uint32_t* mwA = maskS[m0 + g];
    const uint32_t* mwB = maskS[m0 + g + 8];
    int diagA = i0 + m0 + g, diagB = i0 + m0 + g + 8;  // diag already in bitmask
    (void)diagA; (void)diagB;

    float acc[9][4] = {};

    for (int j0 = 0; j0 < CC; j0 += 64) {
        __syncthreads();                       // protect whs reuse
        {   // stage Wh tile, tf32-rounded
            const float4* src = (const float4*)(g_Wh + (size_t)(b * CC + j0) * FF);
#pragma unroll
            for (int p = 0; p < 8; p++) {
                int idx = t + p * 128;
                int row = idx >> 4, c4 = idx & 15;
                float4 v = src[idx];
                v.x = f2tf32f(v.x); v.y = f2tf32f(v.y);
                v.z = f2tf32f(v.z); v.w = f2tf32f(v.w);
                *(float4*)&whs[row][c4 * 4] = v;
            }
        }
        __syncthreads();

#pragma unroll
        for (int kk = 0; kk < 8; kk++) {
            int k0 = kk * 8;
            int jl0 = k0 + tg, jl1 = jl0 + 4;          // both in same 32-bit word
            int wrd = (j0 + k0) >> 5;
            int bit0 = ((j0 + k0) & 31) + tg, bit1 = bit0 + 4;
            uint32_t mA = mwA[wrd], mB = mwB[wrd];
            float s2v0 = s2S[j0 + jl0], s2v1 = s2S[j0 + jl1];

            float xa0 = s1a + s2v0; xa0 = (xa0 > 0.f) ? xa0 : 0.2f * xa0;
            float xa1 = s1a + s2v1; xa1 = (xa1 > 0.f) ? xa1 : 0.2f * xa1;
            float xb0 = s1b + s2v0; xb0 = (xb0 > 0.f) ? xb0 : 0.2f * xb0;
            float xb1 = s1b + s2v1; xb1 = (xb1 > 0.f) ? xb1 : 0.2f * xb1;

            float pa0 = ((mA >> bit0) & 1u) ? __expf(xa0 - ma) : 0.f;
            float pa1 = ((mA >> bit1) & 1u) ? __expf(xa1 - ma) : 0.f;
            float pb0 = ((mB >> bit0) & 1u) ? __expf(xb0 - mb) : 0.f;
            float pb1 = ((mB >> bit1) & 1u) ? __expf(xb1 - mb) : 0.f;

            // A-frag: a0=(row g, k tg) a1=(row g+8, k tg) a2=(row g, k tg+4) a3=(row g+8, k tg+4)
            uint32_t a0 = __float_as_uint(f2tf32f(pa0));
            uint32_t a1 = __float_as_uint(f2tf32f(pb0));
            uint32_t a2 = __float_as_uint(f2tf32f(pa1));
            uint32_t a3 = __float_as_uint(f2tf32f(pb1));

#pragma unroll
            for (int nf = 0; nf < 9; nf++) {
                uint32_t b0 = __float_as_uint(whs[jl0][nf * 8 + g]);
                uint32_t b1 = __float_as_uint(whs[jl1][nf * 8 + g]);
                mma_tf32(acc[nf], a0, a1, a2, a3, b0, b1);
            }
        }
    }

    // epilogue: l = col 64 (nf=8, tg=0 lanes) -> broadcast within quad
    float l_lo = __shfl_sync(0xffffffffu, acc[8][0], lane & ~3);
    float l_hi = __shfl_sync(0xffffffffu, acc[8][2], lane & ~3);
    float inv_lo = 1.f / l_lo;       // l >= 1 guaranteed (exact max in shift)
    float inv_hi = 1.f / l_hi;

    int row_lo = b * CC + i0 + m0 + g;
    int row_hi = row_lo + 8;
#pragma unroll
    for (int nf = 0; nf < 8; nf++) {
        int col = nf * 8 + 2 * tg;
        float2 vlo, vhi;
        vlo.x = fmaxf(acc[nf][0] * inv_lo, 0.f);
        vlo.y = fmaxf(acc[nf][1] * inv_lo, 0.f);
        vhi.x = fmaxf(acc[nf][2] * inv_hi, 0.f);
        vhi.y = fmaxf(acc[nf][3] * inv_hi, 0.f);
        *(float2*)(out + (size_t)row_lo * FF + col) = vlo;
        *(float2*)(out + (size_t)row_hi * FF + col) = vhi;
    }
}

// ---------------------------------------------------------------------------
extern "C" void kernel_launch(void* const* d_in, const int* in_sizes, int n_in,
                              void* d_out, int out_size)
{
    const float* H = (const float*)d_in[0];   // (8, 2048, 128) f32
    const int*   A = (const int*)d_in[1];     // (8, 2048, 2048) i32
    const float* W = (const float*)d_in[2];   // (128, 64) f32
    const float* a = (const float*)d_in[3];   // (128,) f32
    float* out = (float*)d_out;               // (8, 2048, 64) f32

    k_wh<<<NROWS / 128, 256>>>(H, W, a);
    k_out<<<BB * (CC / 64), 128>>>(A, out);
}

// round 6
// speedup vs baseline: 2.6094x; 1.9611x over previous
#include <cuda_runtime.h>
#include <cuda_bf16.h>
#include <cstdint>

#define BB 8
#define CC 2048
#define FIN 128
#define FF 64
#define NROWS (BB*CC)

// Scratch (__device__ globals: allocation-free rule)
__device__ float g_Wh[(size_t)NROWS * FF];   // fp32 Wh
__device__ float g_s1[NROWS];
__device__ float g_s2[NROWS];

__device__ __forceinline__ float f2tf32f(float x) {
    uint32_t r;
    asm("cvt.rna.tf32.f32 %0, %1;" : "=r"(r) : "f"(x));
    return __uint_as_float(r);
}

__device__ __forceinline__ void mma_tf32(float* c,
                                         uint32_t a0, uint32_t a1, uint32_t a2, uint32_t a3,
                                         uint32_t b0, uint32_t b1) {
    asm volatile(
        "mma.sync.aligned.m16n8k8.row.col.f32.tf32.tf32.f32 "
        "{%0,%1,%2,%3}, {%4,%5,%6,%7}, {%8,%9}, {%0,%1,%2,%3};"
        : "+f"(c[0]), "+f"(c[1]), "+f"(c[2]), "+f"(c[3])
        : "r"(a0), "r"(a1), "r"(a2), "r"(a3), "r"(b0), "r"(b1));
}

// ---------------------------------------------------------------------------
// Kernel 1: Wh = H @ W (tiled GEMM, 128 rows/block), + s1 = Wh·a1, s2 = Wh·a2.
// ---------------------------------------------------------------------------
__global__ __launch_bounds__(256) void k_wh(const float* __restrict__ H,
                                            const float* __restrict__ W,
                                            const float* __restrict__ a)
{
    __shared__ float Hs[128][36];
    __shared__ float Ws[32][68];

    int t  = threadIdx.x;
    int tx = t & 15, ty = t >> 4;
    int r0 = blockIdx.x * 128;

    float acc[8][4] = {};

    for (int kc = 0; kc < 4; kc++) {
        __syncthreads();
        {
            int row = t >> 3, q = t & 7;
            const float* src = H + (size_t)r0 * FIN + kc * 32;
#pragma unroll
            for (int p = 0; p < 4; p++) {
                int rr = p * 32 + row;
                *(float4*)&Hs[rr][q * 4] = *(const float4*)(src + (size_t)rr * FIN + q * 4);
            }
        }
        {
#pragma unroll
            for (int p = 0; p < 2; p++) {
                int idx = t + p * 256;
                int row = idx >> 4, c4 = idx & 15;
                *(float4*)&Ws[row][c4 * 4] = *(const float4*)(W + (size_t)(kc * 32 + row) * FF + c4 * 4);
            }
        }
        __syncthreads();

#pragma unroll
        for (int k = 0; k < 32; k++) {
            float4 w = *(const float4*)&Ws[k][tx * 4];
#pragma unroll
            for (int rr = 0; rr < 8; rr++) {
                float h = Hs[ty * 8 + rr][k];
                acc[rr][0] = fmaf(h, w.x, acc[rr][0]);
                acc[rr][1] = fmaf(h, w.y, acc[rr][1]);
                acc[rr][2] = fmaf(h, w.z, acc[rr][2]);
                acc[rr][3] = fmaf(h, w.w, acc[rr][3]);
            }
        }
    }

    float a1v[4], a2v[4];
#pragma unroll
    for (int c = 0; c < 4; c++) { a1v[c] = a[tx * 4 + c]; a2v[c] = a[FF + tx * 4 + c]; }

#pragma unroll
    for (int rr = 0; rr < 8; rr++) {
        int r = r0 + ty * 8 + rr;
        float p1 = 0.f, p2 = 0.f;
#pragma unroll
        for (int c = 0; c < 4; c++) {
            p1 = fmaf(acc[rr][c], a1v[c], p1);
            p2 = fmaf(acc[rr][c], a2v[c], p2);
        }
#pragma unroll
        for (int off = 8; off; off >>= 1) {
            p1 += __shfl_xor_sync(0xffffffffu, p1, off);
            p2 += __shfl_xor_sync(0xffffffffu, p2, off);
        }
        if (tx == 0) { g_s1[r] = p1; g_s2[r] = p2; }

        *(float4*)(g_Wh + (size_t)r * FF + tx * 4) = *(float4*)acc[rr];
    }
}

// ---------------------------------------------------------------------------
// Kernel 2: fused masked-softmax @ Wh.  64 rows/block, 256 threads (8 warps).
// Pass 1: int4-vectorized single read of the 64x2048 A strip -> interleaved
//         bitmask (word=(j>>7)*4+(j&3), bit=(j>>2)&31) + exact per-row max.
// Pass 2: two warp-groups split the j range (even/odd 64-tiles); p computed
//         straight into tf32 MMA A-fragments; ones-column yields l; partial
//         accumulators reduced through smem (aliasing the Wh tile buffer).
// ---------------------------------------------------------------------------
// dynamic smem layout (bytes):
//   maskS : uint32[64][68]        @ 0       (17408)
//   s2S   : float [2048]          @ 17408   (8192)
//   whs   : float [2][64][72]     @ 25600   (36864)   (aliased as accS at end)
//   s1s   : float [64]            @ 62464   (256)
//   ms    : float [64]            @ 62720   (256)
#define KOUT_SMEM 62976

__global__ __launch_bounds__(256) void k_out(const int* __restrict__ A,
                                             float* __restrict__ out)
{
    extern __shared__ char smemraw[];
    uint32_t (*maskS)[68]   = (uint32_t(*)[68])smemraw;
    float* s2S              = (float*)(smemraw + 17408);
    float (*whs)[64][72]    = (float(*)[64][72])(smemraw + 25600);
    float* s1s              = (float*)(smemraw + 62464);
    float* ms               = (float*)(smemraw + 62720);

    int t = threadIdx.x;
    int lane = t & 31;
    int warp = t >> 5;                 // 0..7
    int grp  = t >> 7;                 // 0 or 1 (warp-group)
    int lt   = t & 127;
    int wg   = warp & 3;               // warp within group
    int g = lane >> 2, tg = lane & 3;
    int m0 = wg * 16;

    int b  = blockIdx.x >> 5;
    int i0 = (blockIdx.x & 31) << 6;
    const int* Ab = A + (size_t)b * CC * CC;

    if (t < 64) {
        s1s[t] = g_s1[b * CC + i0 + t];
        // ones column for l (col 64), zero pad 65..71 — written once, both slots
        int slot = 0;
#pragma unroll
        for (slot = 0; slot < 2; slot++) {
            whs[slot][t][64] = 1.f;
#pragma unroll
            for (int c = 65; c < 72; c++) whs[slot][t][c] = 0.f;
        }
    }
    for (int q = t; q < CC; q += 256) s2S[q] = g_s2[b * CC + q];
    __syncthreads();

    // ---- Pass 1: bitmask + exact row max (single int4 read of A) ----
#pragma unroll 1
    for (int rr = 0; rr < 8; rr++) {
        int il = warp * 8 + rr;
        const int4* base4 = (const int4*)(Ab + (size_t)(i0 + il) * CC);
        const float4* s2v4 = (const float4*)s2S;
        int diagj = i0 + il;
        float m2 = -3.0e38f;
#pragma unroll 4
        for (int wd = 0; wd < 16; wd++) {
            int j = wd * 128 + lane * 4;
            int4 av = __ldcs(&base4[wd * 32 + lane]);
            float4 sv = s2v4[wd * 32 + lane];
            bool v0 = (av.x > 0) || (j     == diagj);
            bool v1 = (av.y > 0) || (j + 1 == diagj);
            bool v2 = (av.z > 0) || (j + 2 == diagj);
            bool v3 = (av.w > 0) || (j + 3 == diagj);
            uint32_t b0 = __ballot_sync(0xffffffffu, v0);
            uint32_t b1 = __ballot_sync(0xffffffffu, v1);
            uint32_t b2 = __ballot_sync(0xffffffffu, v2);
            uint32_t b3 = __ballot_sync(0xffffffffu, v3);
            if (lane == 0) {
                maskS[il][wd * 4 + 0] = b0;
                maskS[il][wd * 4 + 1] = b1;
                maskS[il][wd * 4 + 2] = b2;
                maskS[il][wd * 4 + 3] = b3;
            }
            m2 = fmaxf(m2, v0 ? sv.x : -3.0e38f);
            m2 = fmaxf(m2, v1 ? sv.y : -3.0e38f);
            m2 = fmaxf(m2, v2 ? sv.z : -3.0e38f);
            m2 = fmaxf(m2, v3 ? sv.w : -3.0e38f);
        }
#pragma unroll
        for (int off = 16; off; off >>= 1)
            m2 = fmaxf(m2, __shfl_xor_sync(0xffffffffu, m2, off));
        if (lane == 0) {
            float x = s1s[il] + m2;
            ms[il] = (x > 0.f) ? x : 0.2f * x;   // exact row max of lrelu logits
        }
    }
    __syncthreads();

    // hoist row constants for this thread's two MMA rows
    float s1a = s1s[m0 + g],     ma = ms[m0 + g];
    float s1b = s1s[m0 + g + 8], mb = ms[m0 + g + 8];

    float4 acc[9];
#pragma unroll
    for (int nf = 0; nf < 9; nf++) acc[nf] = make_float4(0.f, 0.f, 0.f, 0.f);

    for (int jj = 0; jj < CC; jj += 128) {
        __syncthreads();                       // protect whs reuse
        {   // stage 128 rows of Wh (tf32-rounded) into both slots
            const float4* src = (const float4*)(g_Wh + (size_t)(b * CC + jj) * FF);
#pragma unroll
            for (int p = 0; p < 8; p++) {
                int idx = t + p * 256;
                int row = idx >> 4, c4 = idx & 15;
                float4 v = src[idx];
                v.x = f2tf32f(v.x); v.y = f2tf32f(v.y);
                v.z = f2tf32f(v.z); v.w = f2tf32f(v.w);
                *(float4*)&whs[row >> 6][row & 63][c4 * 4] = v;
            }
        }
        __syncthreads();

        int Bb = jj + grp * 64;                        // this group's j base
        uint32_t mA = maskS[m0 + g][((jj >> 7) << 2) + tg];     // one word covers all kk
        uint32_t mB = maskS[m0 + g + 8][((jj >> 7) << 2) + tg];

#pragma unroll
        for (int kk = 0; kk < 8; kk++) {
            int k0 = kk * 8;
            int jl0 = k0 + tg, jl1 = jl0 + 4;
            int bit0 = grp * 16 + kk * 2, bit1 = bit0 + 1;

            float s2v0 = s2S[Bb + jl0], s2v1 = s2S[Bb + jl1];

            float xa0 = s1a + s2v0; xa0 = (xa0 > 0.f) ? xa0 : 0.2f * xa0;
            float xa1 = s1a + s2v1; xa1 = (xa1 > 0.f) ? xa1 : 0.2f * xa1;
            float xb0 = s1b + s2v0; xb0 = (xb0 > 0.f) ? xb0 : 0.2f * xb0;
            float xb1 = s1b + s2v1; xb1 = (xb1 > 0.f) ? xb1 : 0.2f * xb1;

            float pa0 = ((mA >> bit0) & 1u) ? __expf(xa0 - ma) : 0.f;
            float pa1 = ((mA >> bit1) & 1u) ? __expf(xa1 - ma) : 0.f;
            float pb0 = ((mB >> bit0) & 1u) ? __expf(xb0 - mb) : 0.f;
            float pb1 = ((mB >> bit1) & 1u) ? __expf(xb1 - mb) : 0.f;

            uint32_t a0 = __float_as_uint(f2tf32f(pa0));
            uint32_t a1 = __float_as_uint(f2tf32f(pb0));
            uint32_t a2 = __float_as_uint(f2tf32f(pa1));
            uint32_t a3 = __float_as_uint(f2tf32f(pb1));

#pragma unroll
            for (int nf = 0; nf < 9; nf++) {
                uint32_t b0 = __float_as_uint(whs[grp][jl0][nf * 8 + g]);
                uint32_t b1 = __float_as_uint(whs[grp][jl1][nf * 8 + g]);
                mma_tf32((float*)&acc[nf], a0, a1, a2, a3, b0, b1);
            }
        }
    }

    // ---- cross-group accumulator reduction (alias whs as scratch) ----
    __syncthreads();
    float4* accS = (float4*)whs;
    if (grp == 1) {
#pragma unroll
        for (int nf = 0; nf < 9; nf++) accS[lt * 9 + nf] = acc[nf];
    }
    __syncthreads();
    if (grp == 0) {
#pragma unroll
        for (int nf = 0; nf < 9; nf++) {
            float4 o = accS[lt * 9 + nf];
            acc[nf].x += o.x; acc[nf].y += o.y; acc[nf].z += o.z; acc[nf].w += o.w;
        }

        // epilogue: l = col 64 (nf=8, tg=0 lanes) -> broadcast within quad
        float l_lo = __shfl_sync(0xffffffffu, acc[8].x, lane & ~3);
        float l_hi = __shfl_sync(0xffffffffu, acc[8].z, lane & ~3);
        float inv_lo = 1.f / l_lo;     // l >= 1 guaranteed (exact max shift)
        float inv_hi = 1.f / l_hi;

        int row_lo = b * CC + i0 + m0 + g;
        int row_hi = row_lo + 8;
#pragma unroll
        for (int nf = 0; nf < 8; nf++) {
            int col = nf * 8 + 2 * tg;
            float2 vlo, vhi;
            vlo.x = fmaxf(acc[nf].x * inv_lo, 0.f);
            vlo.y = fmaxf(acc[nf].y * inv_lo, 0.f);
            vhi.x = fmaxf(acc[nf].z * inv_hi, 0.f);
            vhi.y = fmaxf(acc[nf].w * inv_hi, 0.f);
            *(float2*)(out + (size_t)row_lo * FF + col) = vlo;
            *(float2*)(out + (size_t)row_hi * FF + col) = vhi;
        }
    }
}

// ---------------------------------------------------------------------------
extern "C" void kernel_launch(void* const* d_in, const int* in_sizes, int n_in,
                              void* d_out, int out_size)
{
    const float* H = (const float*)d_in[0];   // (8, 2048, 128) f32
    const int*   A = (const int*)d_in[1];     // (8, 2048, 2048) i32
    const float* W = (const float*)d_in[2];   // (128, 64) f32
    const float* a = (const float*)d_in[3];   // (128,) f32
    float* out = (float*)d_out;               // (8, 2048, 64) f32

    cudaFuncSetAttribute(k_out, cudaFuncAttributeMaxDynamicSharedMemorySize, KOUT_SMEM);

    k_wh<<<NROWS / 128, 256>>>(H, W, a);
    k_out<<<BB * (CC / 64), 256, KOUT_SMEM>>>(A, out);
}

// round 7
// speedup vs baseline: 3.2981x; 1.2639x over previous
#include <cuda_runtime.h>
#include <cuda_bf16.h>
#include <cstdint>

#define BB 8
#define CC 2048
#define FIN 128
#define FF 64
#define NROWS (BB*CC)
#define LOG2E 1.4426950408889634f

// Scratch (__device__ globals: allocation-free rule)
__device__ float g_Wh[(size_t)NROWS * FF];    // tf32-rounded Wh
__device__ float g_s1[NROWS];                 // s1 * log2e
__device__ float g_s2[NROWS];                 // s2 * log2e
__device__ float g_part[512][64][72];         // per (tile,half): unnorm acc + l(col 64)
__device__ float g_partm[512][64];            // per (tile,half): row shift m (exp2 domain)

__device__ __forceinline__ float f2tf32f(float x) {
    uint32_t r;
    asm("cvt.rna.tf32.f32 %0, %1;" : "=r"(r) : "f"(x));
    return __uint_as_float(r);
}
__device__ __forceinline__ float ex2f(float x) {
    float r;
    asm("ex2.approx.f32 %0, %1;" : "=f"(r) : "f"(x));
    return r;
}
__device__ __forceinline__ void mma_tf32(float* c,
                                         uint32_t a0, uint32_t a1, uint32_t a2, uint32_t a3,
                                         uint32_t b0, uint32_t b1) {
    asm volatile(
        "mma.sync.aligned.m16n8k8.row.col.f32.tf32.tf32.f32 "
        "{%0,%1,%2,%3}, {%4,%5,%6,%7}, {%8,%9}, {%0,%1,%2,%3};"
        : "+f"(c[0]), "+f"(c[1]), "+f"(c[2]), "+f"(c[3])
        : "r"(a0), "r"(a1), "r"(a2), "r"(a3), "r"(b0), "r"(b1));
}

// ---------------------------------------------------------------------------
// Kernel 1: Wh = H @ W, + s1 = log2e*(Wh·a1), s2 = log2e*(Wh·a2).
// Wh stored tf32-rounded (only the tf32 MMA consumes it).
// ---------------------------------------------------------------------------
__global__ __launch_bounds__(256) void k_wh(const float* __restrict__ H,
                                            const float* __restrict__ W,
                                            const float* __restrict__ a)
{
    __shared__ float Hs[128][36];
    __shared__ float Ws[32][68];

    int t  = threadIdx.x;
    int tx = t & 15, ty = t >> 4;
    int r0 = blockIdx.x * 128;

    float acc[8][4] = {};

    for (int kc = 0; kc < 4; kc++) {
        __syncthreads();
        {
            int row = t >> 3, q = t & 7;
            const float* src = H + (size_t)r0 * FIN + kc * 32;
#pragma unroll
            for (int p = 0; p < 4; p++) {
                int rr = p * 32 + row;
                *(float4*)&Hs[rr][q * 4] = *(const float4*)(src + (size_t)rr * FIN + q * 4);
            }
        }
        {
#pragma unroll
            for (int p = 0; p < 2; p++) {
                int idx = t + p * 256;
                int row = idx >> 4, c4 = idx & 15;
                *(float4*)&Ws[row][c4 * 4] = *(const float4*)(W + (size_t)(kc * 32 + row) * FF + c4 * 4);
            }
        }
        __syncthreads();

#pragma unroll
        for (int k = 0; k < 32; k++) {
            float4 w = *(const float4*)&Ws[k][tx * 4];
#pragma unroll
            for (int rr = 0; rr < 8; rr++) {
                float h = Hs[ty * 8 + rr][k];
                acc[rr][0] = fmaf(h, w.x, acc[rr][0]);
                acc[rr][1] = fmaf(h, w.y, acc[rr][1]);
                acc[rr][2] = fmaf(h, w.z, acc[rr][2]);
                acc[rr][3] = fmaf(h, w.w, acc[rr][3]);
            }
        }
    }

    float a1v[4], a2v[4];
#pragma unroll
    for (int c = 0; c < 4; c++) { a1v[c] = a[tx * 4 + c]; a2v[c] = a[FF + tx * 4 + c]; }

#pragma unroll
    for (int rr = 0; rr < 8; rr++) {
        int r = r0 + ty * 8 + rr;
        float p1 = 0.f, p2 = 0.f;
#pragma unroll
        for (int c = 0; c < 4; c++) {
            p1 = fmaf(acc[rr][c], a1v[c], p1);
            p2 = fmaf(acc[rr][c], a2v[c], p2);
        }
#pragma unroll
        for (int off = 8; off; off >>= 1) {
            p1 += __shfl_xor_sync(0xffffffffu, p1, off);
            p2 += __shfl_xor_sync(0xffffffffu, p2, off);
        }
        if (tx == 0) { g_s1[r] = p1 * LOG2E; g_s2[r] = p2 * LOG2E; }

        float4 v;
        v.x = f2tf32f(acc[rr][0]); v.y = f2tf32f(acc[rr][1]);
        v.z = f2tf32f(acc[rr][2]); v.w = f2tf32f(acc[rr][3]);
        *(float4*)(g_Wh + (size_t)r * FF + tx * 4) = v;
    }
}

// ---------------------------------------------------------------------------
// Kernel 2: split-j partial masked-softmax @ Wh.
// Grid 512: bid -> (tile = bid>>1, half = bid&1); 64 rows x 1024 j per block.
// Pass 1: int4 read of the A strip -> interleaved bitmask + exact local max.
// Pass 2: two warp-groups split the 1024 j; tf32 MMA with ones-column for l.
// Output: unnormalized partial acc + l + m to scratch (combined by k_comb).
// ---------------------------------------------------------------------------
// dynamic smem layout (bytes):
//   maskS : uint32[64][36]      @ 0       (9216)
//   s2S   : float [1024]        @ 9216    (4096)
//   whs   : float [2][64][72]   @ 13312   (36864)  (aliased as accS at end)
//   s1s   : float [64]          @ 50176   (256)
//   ms    : float [64]          @ 50432   (256)
#define KOUT_SMEM 50688

__global__ __launch_bounds__(256) void k_out(const int* __restrict__ A)
{
    extern __shared__ char smemraw[];
    uint32_t (*maskS)[36]   = (uint32_t(*)[36])smemraw;
    float* s2S              = (float*)(smemraw + 9216);
    float (*whs)[64][72]    = (float(*)[64][72])(smemraw + 13312);
    float* s1s              = (float*)(smemraw + 50176);
    float* ms               = (float*)(smemraw + 50432);

    int t = threadIdx.x;
    int lane = t & 31;
    int warp = t >> 5;                 // 0..7
    int grp  = t >> 7;                 // warp-group 0/1
    int lt   = t & 127;
    int wg   = warp & 3;
    int g = lane >> 2, tg = lane & 3;
    int m0 = wg * 16;

    int bid  = blockIdx.x;
    int half = bid & 1;
    int tile = bid >> 1;               // 0..255
    int b  = tile >> 5;
    int i0 = (tile & 31) << 6;
    int J0 = half << 10;               // j base (1024 per half)
    const int* Ab = A + (size_t)b * CC * CC;

    if (t < 64) {
        s1s[t] = g_s1[b * CC + i0 + t];
#pragma unroll
        for (int slot = 0; slot < 2; slot++) {
            whs[slot][t][64] = 1.f;
#pragma unroll
            for (int c = 65; c < 72; c++) whs[slot][t][c] = 0.f;
        }
    }
    for (int q = t; q < 1024; q += 256) s2S[q] = g_s2[b * CC + J0 + q];
    __syncthreads();

    // ---- Pass 1: bitmask + exact local max over this half ----
#pragma unroll 1
    for (int rr = 0; rr < 8; rr++) {
        int il = warp * 8 + rr;
        const int4* base4 = (const int4*)(Ab + (size_t)(i0 + il) * CC + J0);
        const float4* s2v4 = (const float4*)s2S;
        int diagr = (i0 + il) - J0;          // diagonal j relative to this half
        float m2 = -3.0e38f;
#pragma unroll 4
        for (int wd = 0; wd < 8; wd++) {
            int jr = wd * 128 + lane * 4;
            int4 av = __ldcs(&base4[wd * 32 + lane]);
            float4 sv = s2v4[wd * 32 + lane];
            bool v0 = (av.x > 0) || (jr     == diagr);
            bool v1 = (av.y > 0) || (jr + 1 == diagr);
            bool v2 = (av.z > 0) || (jr + 2 == diagr);
            bool v3 = (av.w > 0) || (jr + 3 == diagr);
            uint32_t b0 = __ballot_sync(0xffffffffu, v0);
            uint32_t b1 = __ballot_sync(0xffffffffu, v1);
            uint32_t b2 = __ballot_sync(0xffffffffu, v2);
            uint32_t b3 = __ballot_sync(0xffffffffu, v3);
            if (lane == 0) {
                maskS[il][wd * 4 + 0] = b0;
                maskS[il][wd * 4 + 1] = b1;
                maskS[il][wd * 4 + 2] = b2;
                maskS[il][wd * 4 + 3] = b3;
            }
            m2 = fmaxf(m2, v0 ? sv.x : -3.0e38f);
            m2 = fmaxf(m2, v1 ? sv.y : -3.0e38f);
            m2 = fmaxf(m2, v2 ? sv.z : -3.0e38f);
            m2 = fmaxf(m2, v3 ? sv.w : -3.0e38f);
        }
#pragma unroll
        for (int off = 16; off; off >>= 1)
            m2 = fmaxf(m2, __shfl_xor_sync(0xffffffffu, m2, off));
        if (lane == 0) {
            float x = s1s[il] + m2;
            ms[il] = fmaxf(x, 0.2f * x);        // lrelu (exp2 domain)
        }
    }
    __syncthreads();

    if (t < 64) g_partm[bid][t] = ms[t];

    float s1a = s1s[m0 + g],     ma = ms[m0 + g];
    float s1b = s1s[m0 + g + 8], mb = ms[m0 + g + 8];

    float4 acc[9];
#pragma unroll
    for (int nf = 0; nf < 9; nf++) acc[nf] = make_float4(0.f, 0.f, 0.f, 0.f);

    for (int o = 0; o < 8; o++) {
        __syncthreads();
        {   // stage 128 Wh rows (already tf32)
            const float4* src = (const float4*)(g_Wh + (size_t)(b * CC + J0 + o * 128) * FF);
#pragma unroll
            for (int p = 0; p < 8; p++) {
                int idx = t + p * 256;
                int row = idx >> 4, c4 = idx & 15;
                *(float4*)&whs[row >> 6][row & 63][c4 * 4] = src[idx];
            }
        }
        __syncthreads();

        int Bb = o * 128 + grp * 64;                      // rel j base for group
        uint32_t mA = maskS[m0 + g][o * 4 + tg];
        uint32_t mB = maskS[m0 + g + 8][o * 4 + tg];

#pragma unroll
        for (int kk = 0; kk < 8; kk++) {
            int k0 = kk * 8;
            int jl0 = k0 + tg, jl1 = jl0 + 4;
            int bit0 = grp * 16 + kk * 2, bit1 = bit0 + 1;

            float s2v0 = s2S[Bb + jl0], s2v1 = s2S[Bb + jl1];

            float xa0 = s1a + s2v0; xa0 = fmaxf(xa0, 0.2f * xa0) - ma;
            float xa1 = s1a + s2v1; xa1 = fmaxf(xa1, 0.2f * xa1) - ma;
            float xb0 = s1b + s2v0; xb0 = fmaxf(xb0, 0.2f * xb0) - mb;
            float xb1 = s1b + s2v1; xb1 = fmaxf(xb1, 0.2f * xb1) - mb;

            // select BEFORE the MUFU: invalid -> -1000 -> ex2 = 0
            xa0 = ((mA >> bit0) & 1u) ? xa0 : -1000.f;
            xa1 = ((mA >> bit1) & 1u) ? xa1 : -1000.f;
            xb0 = ((mB >> bit0) & 1u) ? xb0 : -1000.f;
            xb1 = ((mB >> bit1) & 1u) ? xb1 : -1000.f;

            uint32_t a0 = __float_as_uint(f2tf32f(ex2f(xa0)));
            uint32_t a1 = __float_as_uint(f2tf32f(ex2f(xb0)));
            uint32_t a2 = __float_as_uint(f2tf32f(ex2f(xa1)));
            uint32_t a3 = __float_as_uint(f2tf32f(ex2f(xb1)));

#pragma unroll
            for (int nf = 0; nf < 9; nf++) {
                uint32_t b0 = __float_as_uint(whs[grp][jl0][nf * 8 + g]);
                uint32_t b1 = __float_as_uint(whs[grp][jl1][nf * 8 + g]);
                mma_tf32((float*)&acc[nf], a0, a1, a2, a3, b0, b1);
            }
        }
    }

    // ---- cross-group reduction (alias whs) + scratch write ----
    __syncthreads();
    float4* accS = (float4*)whs;
    if (grp == 1) {
#pragma unroll
        for (int nf = 0; nf < 9; nf++) accS[lt * 9 + nf] = acc[nf];
    }
    __syncthreads();
    if (grp == 0) {
#pragma unroll
        for (int nf = 0; nf < 9; nf++) {
            float4 o = accS[lt * 9 + nf];
            acc[nf].x += o.x; acc[nf].y += o.y; acc[nf].z += o.z; acc[nf].w += o.w;
        }
        int row_lo = m0 + g, row_hi = row_lo + 8;
#pragma unroll
        for (int nf = 0; nf < 9; nf++) {
            int col = nf * 8 + 2 * tg;
            *(float2*)&g_part[bid][row_lo][col] = make_float2(acc[nf].x, acc[nf].y);
            *(float2*)&g_part[bid][row_hi][col] = make_float2(acc[nf].z, acc[nf].w);
        }
    }
}

// ---------------------------------------------------------------------------
// Kernel 3: combine the two j-halves: out = relu((Σ acc_h w_h) / (Σ l_h w_h)),
// w_h = exp2(m_h - max(m)).  256 blocks x 256 threads; 4 cols x 16 per thread.
// ---------------------------------------------------------------------------
__global__ __launch_bounds__(256) void k_comb(float* __restrict__ out)
{
    int tile = blockIdx.x;                 // 0..255
    int t = threadIdx.x;
    int ri = t >> 2, cq = t & 3;
    int p0 = tile * 2, p1 = p0 + 1;

    float m0 = g_partm[p0][ri], m1 = g_partm[p1][ri];
    float M = fmaxf(m0, m1);
    float w0 = ex2f(m0 - M), w1 = ex2f(m1 - M);
    float l = g_part[p0][ri][64] * w0 + g_part[p1][ri][64] * w1;
    float inv = 1.f / l;

    size_t rowbase = ((size_t)tile * 64 + ri) * FF;
#pragma unroll
    for (int q = 0; q < 4; q++) {
        int col = cq * 16 + q * 4;
        float4 a0 = *(const float4*)&g_part[p0][ri][col];
        float4 a1 = *(const float4*)&g_part[p1][ri][col];
        float4 v;
        v.x = fmaxf((a0.x * w0 + a1.x * w1) * inv, 0.f);
        v.y = fmaxf((a0.y * w0 + a1.y * w1) * inv, 0.f);
        v.z = fmaxf((a0.z * w0 + a1.z * w1) * inv, 0.f);
        v.w = fmaxf((a0.w * w0 + a1.w * w1) * inv, 0.f);
        *(float4*)(out + rowbase + col) = v;
    }
}

// ---------------------------------------------------------------------------
extern "C" void kernel_launch(void* const* d_in, const int* in_sizes, int n_in,
                              void* d_out, int out_size)
{
    const float* H = (const float*)d_in[0];   // (8, 2048, 128) f32
    const int*   A = (const int*)d_in[1];     // (8, 2048, 2048) i32
    const float* W = (const float*)d_in[2];   // (128, 64) f32
    const float* a = (const float*)d_in[3];   // (128,) f32
    float* out = (float*)d_out;               // (8, 2048, 64) f32

    cudaFuncSetAttribute(k_out, cudaFuncAttributeMaxDynamicSharedMemorySize, KOUT_SMEM);

    k_wh<<<NROWS / 128, 256>>>(H, W, a);
    k_out<<<512, 256, KOUT_SMEM>>>(A);
    k_comb<<<256, 256>>>(out);
}

// round 8
// speedup vs baseline: 3.5009x; 1.0615x over previous
#include <cuda_runtime.h>
#include <cuda_bf16.h>
#include <cstdint>

#define BB 8
#define CC 2048
#define FIN 128
#define FF 64
#define NROWS (BB*CC)
#define LOG2E 1.4426950408889634f

// Scratch (__device__ globals: allocation-free rule)
// g_WhP: paired layout, per 64-row group g (= global row>>6), 4096 floats:
//   offset = g*4096 + kt*128 + col*2 + h,  kt = (q>>3)*4 + (q&3), h = (q>>2)&1,
//   q = row within group. Pair (q, q+4) shares kt, h=0/1. tf32-rounded.
__device__ float g_WhP[(size_t)NROWS * FF];
__device__ float g_s1[NROWS];                 // s1 * log2e
__device__ float g_s2[NROWS];                 // s2 * log2e
__device__ float g_part[512][64][72];         // per (tile,half): unnorm acc + l at col 64
__device__ float g_partm[512][64];            // per (tile,half): row shift m (exp2 domain)

__device__ __forceinline__ float f2tf32f(float x) {
    uint32_t r;
    asm("cvt.rna.tf32.f32 %0, %1;" : "=r"(r) : "f"(x));
    return __uint_as_float(r);
}
__device__ __forceinline__ float ex2f(float x) {
    float r;
    asm("ex2.approx.f32 %0, %1;" : "=f"(r) : "f"(x));
    return r;
}
__device__ __forceinline__ void mma_tf32(float* c,
                                         uint32_t a0, uint32_t a1, uint32_t a2, uint32_t a3,
                                         uint32_t b0, uint32_t b1) {
    asm volatile(
        "mma.sync.aligned.m16n8k8.row.col.f32.tf32.tf32.f32 "
        "{%0,%1,%2,%3}, {%4,%5,%6,%7}, {%8,%9}, {%0,%1,%2,%3};"
        : "+f"(c[0]), "+f"(c[1]), "+f"(c[2]), "+f"(c[3])
        : "r"(a0), "r"(a1), "r"(a2), "r"(a3), "r"(b0), "r"(b1));
}

// permuted row offset inside HsT row-dim: conflict-free LDS.128 for 8-row groups
__device__ __forceinline__ int hperm(int r) { return r + ((r >> 3) << 2); }

// ---------------------------------------------------------------------------
// Kernel 1: Wh = H @ W (64 rows/block, grid 256), + s1,s2 (x log2e).
// HsT: k-major transposed H tile, permuted rows -> conflict-free LDS.128.
// Writes g_WhP in the paired layout, tf32-rounded.
// ---------------------------------------------------------------------------
__global__ __launch_bounds__(256) void k_wh(const float* __restrict__ H,
                                            const float* __restrict__ W,
                                            const float* __restrict__ a)
{
    __shared__ float HsT[32][92];     // [k][perm(row)]  (64 rows -> 0..91)
    __shared__ float Ws[32][68];      // [k][col]

    int t  = threadIdx.x;
    int tx = t & 31;                  // 2 cols: 2tx, 2tx+1
    int ty = t >> 5;                  // 0..7 -> rows ty*8 .. ty*8+7
    int r0 = blockIdx.x * 64;

    float acc[8][2] = {};

    for (int kc = 0; kc < 4; kc++) {
        __syncthreads();
        {   // H tile transposed: rows r0..r0+63, cols kc*32..+31
#pragma unroll
            for (int p = 0; p < 2; p++) {
                int idx = t + p * 256;             // 512 float4
                int r = idx >> 3, c4 = idx & 7;
                float4 v = *(const float4*)(H + (size_t)(r0 + r) * FIN + kc * 32 + c4 * 4);
                int pr = hperm(r);
                HsT[c4 * 4 + 0][pr] = v.x;
                HsT[c4 * 4 + 1][pr] = v.y;
                HsT[c4 * 4 + 2][pr] = v.z;
                HsT[c4 * 4 + 3][pr] = v.w;
            }
        }
        {   // W chunk
#pragma unroll
            for (int p = 0; p < 2; p++) {
                int idx = t + p * 256;
                int row = idx >> 4, c4 = idx & 15;
                *(float4*)&Ws[row][c4 * 4] = *(const float4*)(W + (size_t)(kc * 32 + row) * FF + c4 * 4);
            }
        }
        __syncthreads();

#pragma unroll
        for (int k = 0; k < 32; k++) {
            float2 w = *(const float2*)&Ws[k][tx * 2];
            float4 h0 = *(const float4*)&HsT[k][ty * 12];       // perm(ty*8) = ty*12
            float4 h1 = *(const float4*)&HsT[k][ty * 12 + 4];
            acc[0][0] = fmaf(h0.x, w.x, acc[0][0]); acc[0][1] = fmaf(h0.x, w.y, acc[0][1]);
            acc[1][0] = fmaf(h0.y, w.x, acc[1][0]); acc[1][1] = fmaf(h0.y, w.y, acc[1][1]);
            acc[2][0] = fmaf(h0.z, w.x, acc[2][0]); acc[2][1] = fmaf(h0.z, w.y, acc[2][1]);
            acc[3][0] = fmaf(h0.w, w.x, acc[3][0]); acc[3][1] = fmaf(h0.w, w.y, acc[3][1]);
            acc[4][0] = fmaf(h1.x, w.x, acc[4][0]); acc[4][1] = fmaf(h1.x, w.y, acc[4][1]);
            acc[5][0] = fmaf(h1.y, w.x, acc[5][0]); acc[5][1] = fmaf(h1.y, w.y, acc[5][1]);
            acc[6][0] = fmaf(h1.z, w.x, acc[6][0]); acc[6][1] = fmaf(h1.z, w.y, acc[6][1]);
            acc[7][0] = fmaf(h1.w, w.x, acc[7][0]); acc[7][1] = fmaf(h1.w, w.y, acc[7][1]);
        }
    }

    // epilogue: s1/s2 per row (full-warp reduce), paired tf32 g_WhP writes
    float a10 = a[tx * 2], a11 = a[tx * 2 + 1];
    float a20 = a[FF + tx * 2], a21 = a[FF + tx * 2 + 1];

#pragma unroll
    for (int rr = 0; rr < 8; rr++) {
        int r = r0 + ty * 8 + rr;
        float p1 = acc[rr][0] * a10 + acc[rr][1] * a11;
        float p2 = acc[rr][0] * a20 + acc[rr][1] * a21;
#pragma unroll
        for (int off = 16; off; off >>= 1) {
            p1 += __shfl_xor_sync(0xffffffffu, p1, off);
            p2 += __shfl_xor_sync(0xffffffffu, p2, off);
        }
        if (tx == 0) { g_s1[r] = p1 * LOG2E; g_s2[r] = p2 * LOG2E; }
    }

    float* dst = g_WhP + (size_t)blockIdx.x * 4096;
#pragma unroll
    for (int rr = 0; rr < 4; rr++) {
        int kt = ty * 4 + rr;
        float4 v;
        v.x = f2tf32f(acc[rr][0]);     // row q=ty*8+rr,   col 2tx
        v.y = f2tf32f(acc[rr + 4][0]); // row q+4,         col 2tx
        v.z = f2tf32f(acc[rr][1]);     // row q,           col 2tx+1
        v.w = f2tf32f(acc[rr + 4][1]); // row q+4,         col 2tx+1
        *(float4*)(dst + kt * 128 + tx * 4) = v;
    }
}

// ---------------------------------------------------------------------------
// Kernel 2: split-j partial masked-softmax @ Wh. Grid 512, 4 blocks/SM,
// fully resident in one wave. 64 rows x 1024 j per block.
// ---------------------------------------------------------------------------
// dynamic smem layout (bytes):
//   maskS  : uint32[64][36]       @ 0       (9216)
//   s2S    : float [1024]         @ 9216    (4096)
//   s2pair : float2[128*4]        @ 13312   (4096)
//   whsP   : float [2][32][68][2] @ 17408   (34816)  (aliased as accS at end)
//   s1s    : float [64]           @ 52224   (256)
//   ms     : float [64]           @ 52480   (256)
#define KOUT_SMEM 52736

__global__ __launch_bounds__(256, 4) void k_out(const int* __restrict__ A)
{
    extern __shared__ char smemraw[];
    uint32_t (*maskS)[36] = (uint32_t(*)[36])smemraw;
    float*  s2S    = (float*)(smemraw + 9216);
    float2* s2pair = (float2*)(smemraw + 13312);
    float*  whsP   = (float*)(smemraw + 17408);   // offset: grp*4352 + kt*136 + colpair*2 + h
    float*  s1s    = (float*)(smemraw + 52224);
    float*  ms     = (float*)(smemraw + 52480);

    int t = threadIdx.x;
    int lane = t & 31;
    int warp = t >> 5;
    int grp  = t >> 7;
    int lt   = t & 127;
    int wg   = warp & 3;
    int g = lane >> 2, tg = lane & 3;
    int m0 = wg * 16;

    int bid  = blockIdx.x;
    int half = bid & 1;
    int tile = bid >> 1;
    int b  = tile >> 5;
    int i0 = (tile & 31) << 6;
    int J0 = half << 10;
    const int* Ab = A + (size_t)b * CC * CC;

    if (t < 64) s1s[t] = g_s1[b * CC + i0 + t];
    for (int q = t; q < 1024; q += 256) s2S[q] = g_s2[b * CC + J0 + q];
    __syncthreads();

    // build s2 pairs: (j, j+4) per group-of-8
#pragma unroll
    for (int p = 0; p < 2; p++) {
        int idx = t + p * 256;                 // 512 = 128 gj x 4 tg
        int gj = idx >> 2, tgq = idx & 3;
        s2pair[idx] = make_float2(s2S[gj * 8 + tgq], s2S[gj * 8 + tgq + 4]);
    }

    // ---- Pass 1: bitmask + exact local max over this half ----
#pragma unroll 1
    for (int rr = 0; rr < 8; rr++) {
        int il = warp * 8 + rr;
        const int4* base4 = (const int4*)(Ab + (size_t)(i0 + il) * CC + J0);
        const float4* s2v4 = (const float4*)s2S;
        int diagr = (i0 + il) - J0;
        float m2 = -3.0e38f;
#pragma unroll 4
        for (int wd = 0; wd < 8; wd++) {
            int jr = wd * 128 + lane * 4;
            int4 av = __ldcs(&base4[wd * 32 + lane]);
            float4 sv = s2v4[wd * 32 + lane];
            bool v0 = (av.x > 0) || (jr     == diagr);
            bool v1 = (av.y > 0) || (jr + 1 == diagr);
            bool v2 = (av.z > 0) || (jr + 2 == diagr);
            bool v3 = (av.w > 0) || (jr + 3 == diagr);
            uint32_t b0 = __ballot_sync(0xffffffffu, v0);
            uint32_t b1 = __ballot_sync(0xffffffffu, v1);
            uint32_t b2 = __ballot_sync(0xffffffffu, v2);
            uint32_t b3 = __ballot_sync(0xffffffffu, v3);
            if (lane == 0) {
                maskS[il][wd * 4 + 0] = b0;
                maskS[il][wd * 4 + 1] = b1;
                maskS[il][wd * 4 + 2] = b2;
                maskS[il][wd * 4 + 3] = b3;
            }
            m2 = fmaxf(m2, v0 ? sv.x : -3.0e38f);
            m2 = fmaxf(m2, v1 ? sv.y : -3.0e38f);
            m2 = fmaxf(m2, v2 ? sv.z : -3.0e38f);
            m2 = fmaxf(m2, v3 ? sv.w : -3.0e38f);
        }
#pragma unroll
        for (int off = 16; off; off >>= 1)
            m2 = fmaxf(m2, __shfl_xor_sync(0xffffffffu, m2, off));
        if (lane == 0) {
            float x = s1s[il] + m2;
            ms[il] = fmaxf(x, 0.2f * x);        // exact row max (exp2 domain)
        }
    }
    __syncthreads();

    if (t < 64) g_partm[bid][t] = ms[t];

    // folded row constants: lrelu(s1+s2)-m = max(s2 + (s1-m), 0.2*s2 + (0.2*s1-m))
    float cA  = s1s[m0 + g]            - ms[m0 + g];
    float c5A = 0.2f * s1s[m0 + g]     - ms[m0 + g];
    float cB  = s1s[m0 + g + 8]        - ms[m0 + g + 8];
    float c5B = 0.2f * s1s[m0 + g + 8] - ms[m0 + g + 8];

    float4 acc[8];
#pragma unroll
    for (int nf = 0; nf < 8; nf++) acc[nf] = make_float4(0.f, 0.f, 0.f, 0.f);
    float lA = 0.f, lB = 0.f;

    int gbase = (b * 32) + (J0 >> 6);          // first 64-row group of this half

    for (int o = 0; o < 8; o++) {
        __syncthreads();
        {   // stage 128 Wh rows (paired layout, straight copy)
            const float4* src = (const float4*)(g_WhP + (size_t)(gbase + o * 2) * 4096);
#pragma unroll
            for (int p = 0; p < 8; p++) {
                int idx = t + p * 256;                   // 2048 float4
                int gs = idx >> 10, rest = idx & 1023;   // rest: kt*32 + f4i
                int kt = rest >> 5, f4i = rest & 31;
                *(float4*)(whsP + gs * 4352 + kt * 136 + f4i * 4) = src[idx];
            }
        }
        __syncthreads();

        uint32_t mA = maskS[m0 + g][o * 4 + tg];
        uint32_t mB = maskS[m0 + g + 8][o * 4 + tg];
        const float2* s2pg = s2pair + ((o * 128 + grp * 64) >> 3) * 4 + tg;
        const float*  wpg  = whsP + grp * 4352 + tg * 136;

#pragma unroll
        for (int kk = 0; kk < 8; kk++) {
            float2 sp = s2pg[kk * 4];                       // {s2[j], s2[j+4]}
            int bit0 = grp * 16 + kk * 2, bit1 = bit0 + 1;

            float ya0 = fmaxf(sp.x + cA, fmaf(0.2f, sp.x, c5A));
            float ya1 = fmaxf(sp.y + cA, fmaf(0.2f, sp.y, c5A));
            float yb0 = fmaxf(sp.x + cB, fmaf(0.2f, sp.x, c5B));
            float yb1 = fmaxf(sp.y + cB, fmaf(0.2f, sp.y, c5B));

            ya0 = ((mA >> bit0) & 1u) ? ya0 : -1000.f;
            ya1 = ((mA >> bit1) & 1u) ? ya1 : -1000.f;
            yb0 = ((mB >> bit0) & 1u) ? yb0 : -1000.f;
            yb1 = ((mB >> bit1) & 1u) ? yb1 : -1000.f;

            float pa0 = f2tf32f(ex2f(ya0));
            float pa1 = f2tf32f(ex2f(ya1));
            float pb0 = f2tf32f(ex2f(yb0));
            float pb1 = f2tf32f(ex2f(yb1));
            lA += pa0 + pa1;
            lB += pb0 + pb1;

            uint32_t a0 = __float_as_uint(pa0);
            uint32_t a1 = __float_as_uint(pb0);
            uint32_t a2 = __float_as_uint(pa1);
            uint32_t a3 = __float_as_uint(pb1);

            const float* wk = wpg + kk * 4 * 136 + g * 2;   // colpair base for this (kk,tg,g)
#pragma unroll
            for (int nf = 0; nf < 8; nf++) {
                float2 wp = *(const float2*)(wk + nf * 16);  // cols pair (jl0,jl1)
                mma_tf32((float*)&acc[nf],
                         a0, a1, a2, a3,
                         __float_as_uint(wp.x), __float_as_uint(wp.y));
            }
        }
    }

    // ---- cross-group reduction (alias whsP) + scratch write ----
    __syncthreads();
    float4* accS = (float4*)whsP;
    if (grp == 1) {
#pragma unroll
        for (int nf = 0; nf < 8; nf++) accS[lt * 9 + nf] = acc[nf];
        accS[lt * 9 + 8] = make_float4(lA, lB, 0.f, 0.f);
    }
    __syncthreads();
    if (grp == 0) {
#pragma unroll
        for (int nf = 0; nf < 8; nf++) {
            float4 o = accS[lt * 9 + nf];
            acc[nf].x += o.x; acc[nf].y += o.y; acc[nf].z += o.z; acc[nf].w += o.w;
        }
        float4 lo = accS[lt * 9 + 8];
        lA += lo.x; lB += lo.y;
        // quad reduce over tg (lane bits 0-1)
        lA += __shfl_xor_sync(0xffffffffu, lA, 1);
        lA += __shfl_xor_sync(0xffffffffu, lA, 2);
        lB += __shfl_xor_sync(0xffffffffu, lB, 1);
        lB += __shfl_xor_sync(0xffffffffu, lB, 2);

        int row_lo = m0 + g, row_hi = row_lo + 8;
#pragma unroll
        for (int nf = 0; nf < 8; nf++) {
            int col = nf * 8 + 2 * tg;
            *(float2*)&g_part[bid][row_lo][col] = make_float2(acc[nf].x, acc[nf].y);
            *(float2*)&g_part[bid][row_hi][col] = make_float2(acc[nf].z, acc[nf].w);
        }
        if (tg == 0) {
            g_part[bid][row_lo][64] = lA;
            g_part[bid][row_hi][64] = lB;
        }
    }
}

// ---------------------------------------------------------------------------
// Kernel 3: combine halves: out = relu((Σ acc_h w_h) / (Σ l_h w_h)),
// w_h = exp2(m_h - max(m)).
// ---------------------------------------------------------------------------
__global__ __launch_bounds__(256) void k_comb(float* __restrict__ out)
{
    int tile = blockIdx.x;
    int t = threadIdx.x;
    int ri = t >> 2, cq = t & 3;
    int p0 = tile * 2, p1 = p0 + 1;

    float m0 = g_partm[p0][ri], m1 = g_partm[p1][ri];
    float M = fmaxf(m0, m1);
    float w0 = ex2f(m0 - M), w1 = ex2f(m1 - M);
    float l = g_part[p0][ri][64] * w0 + g_part[p1][ri][64] * w1;
    float inv = 1.f / l;

    size_t rowbase = ((size_t)tile * 64 + ri) * FF;
#pragma unroll
    for (int q = 0; q < 4; q++) {
        int col = cq * 16 + q * 4;
        float4 a0 = *(const float4*)&g_part[p0][ri][col];
        float4 a1 = *(const float4*)&g_part[p1][ri][col];
        float4 v;
        v.x = fmaxf((a0.x * w0 + a1.x * w1) * inv, 0.f);
        v.y = fmaxf((a0.y * w0 + a1.y * w1) * inv, 0.f);
        v.z = fmaxf((a0.z * w0 + a1.z * w1) * inv, 0.f);
        v.w = fmaxf((a0.w * w0 + a1.w * w1) * inv, 0.f);
        *(float4*)(out + rowbase + col) = v;
    }
}

// ---------------------------------------------------------------------------
extern "C" void kernel_launch(void* const* d_in, const int* in_sizes, int n_in,
                              void* d_out, int out_size)
{
    const float* H = (const float*)d_in[0];   // (8, 2048, 128) f32
    const int*   A = (const int*)d_in[1];     // (8, 2048, 2048) i32
    const float* W = (const float*)d_in[2];   // (128, 64) f32
    const float* a = (const float*)d_in[3];   // (128,) f32
    float* out = (float*)d_out;               // (8, 2048, 64) f32

    cudaFuncSetAttribute(k_out, cudaFuncAttributeMaxDynamicSharedMemorySize, KOUT_SMEM);

    k_wh<<<NROWS / 64, 256>>>(H, W, a);
    k_out<<<512, 256, KOUT_SMEM>>>(A);
    k_comb<<<256, 256>>>(out);
}